// round 4
// baseline (speedup 1.0000x reference)
#include <cuda_runtime.h>
#include <math.h>

#define HID   2048
#define INTER 8192
#define QKV   8192
#define TV    4096
#define NVH   32
#define KD    128
#define VD    128
#define NKH   16
#define CK    4

// ---------------- scratch (device globals; no allocations allowed) ----------
__device__ float g_h[HID];                 // rmsnorm(x)
__device__ float g_proj[QKV + TV + 2*NVH]; // in_proj output
__device__ float g_conv[QKV];              // silu(conv) output
__device__ float g_ygated[TV];             // gated per-head outputs
__device__ float g_x1[HID];                // residual + attn_out
__device__ float g_hn[HID];                // rmsnorm(x1)
__device__ float g_inter[INTER];           // silu(gate)*up

__device__ __forceinline__ float warp_sum(float v) {
#pragma unroll
    for (int o = 16; o; o >>= 1) v += __shfl_down_sync(0xffffffffu, v, o);
    return v;
}

__device__ __forceinline__ float silu(float x) { return x / (1.f + expf(-x)); }

// ---------------- rmsnorm: out = x * rsqrt(mean(x^2)+eps) * (1+w) ----------
__global__ void rmsnorm_k(const float* __restrict__ x, const float* __restrict__ w,
                          float* __restrict__ out) {
    __shared__ float red[8];
    __shared__ float s_inv;
    int tid = threadIdx.x;
    float ss = 0.f;
    for (int i = tid; i < HID; i += blockDim.x) { float v = x[i]; ss += v * v; }
    ss = warp_sum(ss);
    if ((tid & 31) == 0) red[tid >> 5] = ss;
    __syncthreads();
    if (tid == 0) {
        float t = 0.f;
        for (int i = 0; i < (int)(blockDim.x >> 5); i++) t += red[i];
        s_inv = rsqrtf(t / HID + 1e-6f);
    }
    __syncthreads();
    float inv = s_inv;
    for (int i = tid; i < HID; i += blockDim.x)
        out[i] = x[i] * inv * (1.f + w[i]);
}

// ---------------- warp-per-row matvec: y[r] = dot(W[r,:K], v) --------------
template <int K, bool RES>
__global__ void matvec_k(const float* __restrict__ W, const float* __restrict__ v,
                         const float* __restrict__ res, float* __restrict__ y, int rows) {
    int w = (blockIdx.x * blockDim.x + threadIdx.x) >> 5;
    if (w >= rows) return;
    int lane = threadIdx.x & 31;
    const float4* Wr = (const float4*)(W + (size_t)w * K);
    const float4* v4 = (const float4*)v;
    float s = 0.f;
#pragma unroll 8
    for (int i = lane; i < K / 4; i += 32) {
        float4 a = Wr[i];
        float4 b = __ldg(&v4[i]);
        s += a.x * b.x + a.y * b.y + a.z * b.z + a.w * b.w;
    }
    s = warp_sum(s);
    if (lane == 0) y[w] = RES ? (res[w] + s) : s;
}

// ---------------- conv update: shift state, depthwise conv, silu ----------
__global__ void conv_k(const float* __restrict__ cs, const float* __restrict__ cw,
                       float* __restrict__ out_conv_state) {
    int i = blockIdx.x * blockDim.x + threadIdx.x;
    if (i >= QKV) return;
    float s1 = cs[i * 4 + 1], s2 = cs[i * 4 + 2], s3 = cs[i * 4 + 3];
    float xn = g_proj[i];
    float4 w = ((const float4*)cw)[i];
    float acc = s1 * w.x + s2 * w.y + s3 * w.z + xn * w.w;
    ((float4*)out_conv_state)[i] = make_float4(s1, s2, s3, xn);
    g_conv[i] = silu(acc);
}

// ---------------- delta rule per head + gated rmsnorm ----------------------
// block = 1 head (128 threads, thread t owns output column v=t)
__global__ void delta_k(const float* __restrict__ Sin, const float* __restrict__ A_log,
                        const float* __restrict__ dt_bias, const float* __restrict__ norm_w,
                        float* __restrict__ Sout) {
    __shared__ float kn[KD], qn[KD], red[4];
    int h = blockIdx.x;
    int t = threadIdx.x;
    int kh = h >> 1;  // RATIO = 2

    float qv = g_conv[kh * KD + t];
    float kv = g_conv[NKH * KD + kh * KD + t];
    float vv = g_conv[2 * NKH * KD + h * VD + t];

    // l2norm(q)
    float s = warp_sum(qv * qv);
    if ((t & 31) == 0) red[t >> 5] = s;
    __syncthreads();
    float qs = red[0] + red[1] + red[2] + red[3];
    qn[t] = qv / fmaxf(sqrtf(qs), 1e-12f);
    __syncthreads();

    // l2norm(k)
    s = warp_sum(kv * kv);
    if ((t & 31) == 0) red[t >> 5] = s;
    __syncthreads();
    float ks = red[0] + red[1] + red[2] + red[3];
    kn[t] = kv / fmaxf(sqrtf(ks), 1e-12f);
    __syncthreads();

    // per-head scalars
    float a = g_proj[QKV + TV + h];
    float b = g_proj[QKV + TV + NVH + h];
    float beta = 1.f / (1.f + expf(-b));
    float spx = a + dt_bias[h];
    float sp = (spx > 20.f) ? spx : log1pf(expf(spx));
    float decay = expf(-expf(A_log[h]) * sp);

    const float* S  = Sin  + (size_t)h * KD * VD;
    float*       So = Sout + (size_t)h * KD * VD;

    // pass 1: Sk[t] = sum_k S[k,t]*kn[k]
    float Sk = 0.f;
#pragma unroll 8
    for (int k = 0; k < KD; k++) Sk += S[k * VD + t] * kn[k];
    float delta = vv - Sk;

    // pass 2 (L2-hot): newS + y
    float y = 0.f;
#pragma unroll 8
    for (int k = 0; k < KD; k++) {
        float ns = decay * S[k * VD + t] + beta * kn[k] * delta;
        So[k * VD + t] = ns;
        y += ns * qn[k];
    }

    // rmsnorm(y) * norm_w, gate with silu(z)
    __syncthreads();
    s = warp_sum(y * y);
    if ((t & 31) == 0) red[t >> 5] = s;
    __syncthreads();
    float var = (red[0] + red[1] + red[2] + red[3]) / VD;
    float yn = y * rsqrtf(var + 1e-6f) * norm_w[t];
    float z = g_proj[QKV + h * VD + t];
    g_ygated[h * VD + t] = yn * silu(z);
}

// ---------------- gate/up fused matvec: inter = silu(G.hn) * (U.hn) -------
__global__ void gateup_k(const float* __restrict__ G, const float* __restrict__ U) {
    int j = (blockIdx.x * blockDim.x + threadIdx.x) >> 5;
    if (j >= INTER) return;
    int lane = threadIdx.x & 31;
    const float4* g4 = (const float4*)(G + (size_t)j * HID);
    const float4* u4 = (const float4*)(U + (size_t)j * HID);
    const float4* h4 = (const float4*)g_hn;
    float sg = 0.f, su = 0.f;
#pragma unroll 8
    for (int i = lane; i < HID / 4; i += 32) {
        float4 a = g4[i], b = u4[i], c = __ldg(&h4[i]);
        sg += a.x * c.x + a.y * c.y + a.z * c.z + a.w * c.w;
        su += b.x * c.x + b.y * c.y + b.z * c.z + b.w * c.w;
    }
    sg = warp_sum(sg);
    su = warp_sum(su);
    if (lane == 0) g_inter[j] = silu(sg) * su;
}

extern "C" void kernel_launch(void* const* d_in, const int* in_sizes, int n_in,
                              void* d_out, int out_size) {
    const float* x          = (const float*)d_in[0];
    const float* conv_state = (const float*)d_in[1];
    const float* ssm_state  = (const float*)d_in[2];
    const float* in_ln_w    = (const float*)d_in[3];
    const float* in_proj_w  = (const float*)d_in[4];
    const float* conv_w     = (const float*)d_in[5];
    const float* A_log      = (const float*)d_in[6];
    const float* dt_bias    = (const float*)d_in[7];
    const float* norm_w     = (const float*)d_in[8];
    const float* out_proj_w = (const float*)d_in[9];
    const float* post_ln_w  = (const float*)d_in[10];
    const float* gate_w     = (const float*)d_in[11];
    const float* up_w       = (const float*)d_in[12];
    const float* down_w     = (const float*)d_in[13];

    float* out        = (float*)d_out;
    float* out_x      = out;                       // 2048
    float* out_conv   = out + HID;                 // 32768
    float* out_ssm    = out + HID + QKV * CK;      // 524288

    float *p_h, *p_proj, *p_x1, *p_hn, *p_inter, *p_yg;
    cudaGetSymbolAddress((void**)&p_h,     g_h);
    cudaGetSymbolAddress((void**)&p_proj,  g_proj);
    cudaGetSymbolAddress((void**)&p_x1,    g_x1);
    cudaGetSymbolAddress((void**)&p_hn,    g_hn);
    cudaGetSymbolAddress((void**)&p_inter, g_inter);
    cudaGetSymbolAddress((void**)&p_yg,    g_ygated);

    const int ROWS_INPROJ = QKV + TV + 2 * NVH;  // 12352

    // 1. h = rmsnorm(x, in_ln_w)
    rmsnorm_k<<<1, 256>>>(x, in_ln_w, p_h);
    // 2. proj = in_proj_w @ h   (12352 x 2048)
    matvec_k<HID, false><<<(ROWS_INPROJ * 32 + 255) / 256, 256>>>(
        in_proj_w, p_h, nullptr, p_proj, ROWS_INPROJ);
    // 3. conv state shift + depthwise conv + silu
    conv_k<<<QKV / 256, 256>>>(conv_state, conv_w, out_conv);
    // 4. per-head delta rule + gated rmsnorm -> g_ygated, new ssm state
    delta_k<<<NVH, KD>>>(ssm_state, A_log, dt_bias, norm_w, out_ssm);
    // 5. x1 = x + out_proj_w @ y_gated   (2048 x 4096)
    matvec_k<TV, true><<<(HID * 32 + 255) / 256, 256>>>(
        out_proj_w, p_yg, x, p_x1, HID);
    // 6. hn = rmsnorm(x1, post_ln_w)
    rmsnorm_k<<<1, 256>>>(p_x1, post_ln_w, p_hn);
    // 7. inter = silu(gate_w@hn) * (up_w@hn)   (2 x 8192 x 2048)
    gateup_k<<<(INTER * 32 + 255) / 256, 256>>>(gate_w, up_w);
    // 8. x_out = x1 + down_w @ inter   (2048 x 8192)
    matvec_k<INTER, true><<<(HID * 32 + 255) / 256, 256>>>(
        down_w, p_inter, p_x1, out_x, HID);
}

// round 5
// speedup vs baseline: 1.0561x; 1.0561x over previous
#include <cuda_runtime.h>
#include <math.h>

#define HID   2048
#define INTER 8192
#define QKV   8192
#define TV    4096
#define NVH   32
#define KD    128
#define VD    128
#define NKH   16
#define CK    4

// ---------------- scratch (device globals; no allocations allowed) ----------
__device__ float g_h[HID];                 // rmsnorm(x)
__device__ float g_proj[QKV + TV + 2*NVH]; // in_proj output
__device__ float g_conv[QKV];              // silu(conv) output
__device__ float g_ygated[TV];             // gated per-head outputs
__device__ float g_x1[HID];                // residual + attn_out
__device__ float g_hn[HID];                // rmsnorm(x1)
__device__ float g_inter[INTER];           // silu(gate)*up

__device__ __forceinline__ float warp_sum(float v) {
#pragma unroll
    for (int o = 16; o; o >>= 1) v += __shfl_down_sync(0xffffffffu, v, o);
    return v;
}

__device__ __forceinline__ float silu(float x) { return x / (1.f + expf(-x)); }

// ---------------- rmsnorm: out = x * rsqrt(mean(x^2)+eps) * (1+w) ----------
__global__ void rmsnorm_k(const float* __restrict__ x, const float* __restrict__ w,
                          float* __restrict__ out) {
    __shared__ float red[16];
    __shared__ float s_inv;
    int tid = threadIdx.x;
    float ss = 0.f;
    for (int i = tid; i < HID; i += blockDim.x) { float v = x[i]; ss += v * v; }
    ss = warp_sum(ss);
    if ((tid & 31) == 0) red[tid >> 5] = ss;
    __syncthreads();
    if (tid == 0) {
        float t = 0.f;
        for (int i = 0; i < (int)(blockDim.x >> 5); i++) t += red[i];
        s_inv = rsqrtf(t / HID + 1e-6f);
    }
    __syncthreads();
    float inv = s_inv;
    for (int i = tid; i < HID; i += blockDim.x)
        out[i] = x[i] * inv * (1.f + w[i]);
}

// ---------------- warp-per-row matvec: y[r] = dot(W[r,:K], v) --------------
template <int K, bool RES>
__global__ void matvec_k(const float* __restrict__ W, const float* __restrict__ v,
                         const float* __restrict__ res, float* __restrict__ y, int rows) {
    int w = (blockIdx.x * blockDim.x + threadIdx.x) >> 5;
    if (w >= rows) return;
    int lane = threadIdx.x & 31;
    const float4* Wr = (const float4*)(W + (size_t)w * K);
    const float4* v4 = (const float4*)v;
    float s = 0.f;
#pragma unroll
    for (int i = 0; i < K / 128; i++) {
        float4 a = Wr[lane + 32 * i];
        float4 b = __ldg(&v4[lane + 32 * i]);
        s += a.x * b.x + a.y * b.y + a.z * b.z + a.w * b.w;
    }
    s = warp_sum(s);
    if (lane == 0) y[w] = RES ? (res[w] + s) : s;
}

// ---------------- in_proj matvec with fused conv-state update --------------
// rows [0, QKV): mixed_qkv -> conv shift + depthwise conv + silu -> g_conv
// rows [QKV, 12352): z / a / b -> g_proj only
__global__ void inproj_conv_k(const float* __restrict__ W, const float* __restrict__ v,
                              const float* __restrict__ cs, const float* __restrict__ cw,
                              float* __restrict__ out_conv_state, int rows) {
    int r = (blockIdx.x * blockDim.x + threadIdx.x) >> 5;
    if (r >= rows) return;
    int lane = threadIdx.x & 31;
    const float4* Wr = (const float4*)(W + (size_t)r * HID);
    const float4* v4 = (const float4*)v;
    float s = 0.f;
#pragma unroll
    for (int i = 0; i < HID / 128; i++) {
        float4 a = Wr[lane + 32 * i];
        float4 b = __ldg(&v4[lane + 32 * i]);
        s += a.x * b.x + a.y * b.y + a.z * b.z + a.w * b.w;
    }
    s = warp_sum(s);
    if (lane == 0) {
        g_proj[r] = s;
        if (r < QKV) {
            float s1 = cs[r * 4 + 1], s2 = cs[r * 4 + 2], s3 = cs[r * 4 + 3];
            float4 w4 = ((const float4*)cw)[r];
            float acc = s1 * w4.x + s2 * w4.y + s3 * w4.z + s * w4.w;
            ((float4*)out_conv_state)[r] = make_float4(s1, s2, s3, s);
            g_conv[r] = silu(acc);
        }
    }
}

// ---------------- delta rule per head + gated rmsnorm ----------------------
// block = 1 head, 1024 threads. S (128x128) staged in dynamic SMEM.
// Thread map: tid = t + 128*kg, t = output column, kg in [0,8) = k-chunk.
__global__ void delta_k(const float* __restrict__ Sin, const float* __restrict__ A_log,
                        const float* __restrict__ dt_bias, const float* __restrict__ norm_w,
                        float* __restrict__ Sout) {
    extern __shared__ float sm[];
    float* Ssh  = sm;                    // 16384
    float* kn   = sm + KD * VD;          // 128
    float* qn   = kn + KD;               // 128
    float* dl   = qn + KD;               // 128
    float* part = dl + KD;               // 1024
    float* red  = part + 1024;           // 4

    int h   = blockIdx.x;
    int tid = threadIdx.x;
    int t   = tid & 127;
    int kg  = tid >> 7;
    int kh  = h >> 1;  // RATIO = 2

    // stage S into shared (coalesced float4)
    const float4* S4 = (const float4*)(Sin + (size_t)h * KD * VD);
#pragma unroll
    for (int i = 0; i < 4; i++)
        ((float4*)Ssh)[tid + 1024 * i] = S4[tid + 1024 * i];

    // l2norm(q), l2norm(k) computed by first 128 threads
    float qv = 0.f, kv = 0.f, vv = 0.f;
    if (tid < 128) {
        qv = g_conv[kh * KD + t];
        kv = g_conv[NKH * KD + kh * KD + t];
        vv = g_conv[2 * NKH * KD + h * VD + t];
        float s = warp_sum(qv * qv);
        if ((t & 31) == 0) red[t >> 5] = s;
    }
    __syncthreads();
    if (tid < 128) {
        float qs = red[0] + red[1] + red[2] + red[3];
        qn[t] = qv / fmaxf(sqrtf(qs), 1e-12f);
    }
    __syncthreads();
    if (tid < 128) {
        float s = warp_sum(kv * kv);
        if ((t & 31) == 0) red[t >> 5] = s;
    }
    __syncthreads();
    if (tid < 128) {
        float ks = red[0] + red[1] + red[2] + red[3];
        kn[t] = kv / fmaxf(sqrtf(ks), 1e-12f);
    }
    __syncthreads();

    // per-head scalars (cheap, every thread)
    float a = g_proj[QKV + TV + h];
    float b = g_proj[QKV + TV + NVH + h];
    float beta = 1.f / (1.f + expf(-b));
    float spx = a + dt_bias[h];
    float sp = (spx > 20.f) ? spx : log1pf(expf(spx));
    float decay = expf(-expf(A_log[h]) * sp);

    // pass 1: Sk[t] = sum_k S[k,t]*kn[k], k split over 8 groups
    {
        float s = 0.f;
        int k0 = kg * 16;
#pragma unroll
        for (int k = 0; k < 16; k++) s += Ssh[(k0 + k) * VD + t] * kn[k0 + k];
        part[kg * 128 + t] = s;
    }
    __syncthreads();
    if (tid < 128) {
        float sk = 0.f;
#pragma unroll
        for (int g = 0; g < 8; g++) sk += part[g * 128 + t];
        dl[t] = vv - sk;
    }
    __syncthreads();

    // pass 2: newS (write global) + y partials
    float* So = Sout + (size_t)h * KD * VD;
    {
        float del = dl[t];
        float yp = 0.f;
        int k0 = kg * 16;
#pragma unroll
        for (int k = 0; k < 16; k++) {
            int kk = k0 + k;
            float ns = decay * Ssh[kk * VD + t] + beta * kn[kk] * del;
            So[kk * VD + t] = ns;
            yp += ns * qn[kk];
        }
        part[kg * 128 + t] = yp;
    }
    __syncthreads();

    // y, rmsnorm(y)*norm_w, gate with silu(z) -- first 128 threads
    float y = 0.f;
    if (tid < 128) {
#pragma unroll
        for (int g = 0; g < 8; g++) y += part[g * 128 + t];
        float s = warp_sum(y * y);
        if ((t & 31) == 0) red[t >> 5] = s;
    }
    __syncthreads();
    if (tid < 128) {
        float var = (red[0] + red[1] + red[2] + red[3]) / VD;
        float yn = y * rsqrtf(var + 1e-6f) * norm_w[t];
        float z = g_proj[QKV + h * VD + t];
        g_ygated[h * VD + t] = yn * silu(z);
    }
}

// ---------------- gate/up fused matvec: inter = silu(G.hn) * (U.hn) -------
__global__ void gateup_k(const float* __restrict__ G, const float* __restrict__ U) {
    int j = (blockIdx.x * blockDim.x + threadIdx.x) >> 5;
    if (j >= INTER) return;
    int lane = threadIdx.x & 31;
    const float4* g4 = (const float4*)(G + (size_t)j * HID);
    const float4* u4 = (const float4*)(U + (size_t)j * HID);
    const float4* h4 = (const float4*)g_hn;
    float sg = 0.f, su = 0.f;
#pragma unroll
    for (int i = 0; i < HID / 128; i++) {
        float4 a = g4[lane + 32 * i], b = u4[lane + 32 * i], c = __ldg(&h4[lane + 32 * i]);
        sg += a.x * c.x + a.y * c.y + a.z * c.z + a.w * c.w;
        su += b.x * c.x + b.y * c.y + b.z * c.z + b.w * c.w;
    }
    sg = warp_sum(sg);
    su = warp_sum(su);
    if (lane == 0) g_inter[j] = silu(sg) * su;
}

extern "C" void kernel_launch(void* const* d_in, const int* in_sizes, int n_in,
                              void* d_out, int out_size) {
    const float* x          = (const float*)d_in[0];
    const float* conv_state = (const float*)d_in[1];
    const float* ssm_state  = (const float*)d_in[2];
    const float* in_ln_w    = (const float*)d_in[3];
    const float* in_proj_w  = (const float*)d_in[4];
    const float* conv_w     = (const float*)d_in[5];
    const float* A_log      = (const float*)d_in[6];
    const float* dt_bias    = (const float*)d_in[7];
    const float* norm_w     = (const float*)d_in[8];
    const float* out_proj_w = (const float*)d_in[9];
    const float* post_ln_w  = (const float*)d_in[10];
    const float* gate_w     = (const float*)d_in[11];
    const float* up_w       = (const float*)d_in[12];
    const float* down_w     = (const float*)d_in[13];

    float* out        = (float*)d_out;
    float* out_x      = out;                       // 2048
    float* out_conv   = out + HID;                 // 32768
    float* out_ssm    = out + HID + QKV * CK;      // 524288

    float *p_h, *p_x1, *p_hn, *p_inter, *p_yg;
    cudaGetSymbolAddress((void**)&p_h,     g_h);
    cudaGetSymbolAddress((void**)&p_x1,    g_x1);
    cudaGetSymbolAddress((void**)&p_hn,    g_hn);
    cudaGetSymbolAddress((void**)&p_inter, g_inter);
    cudaGetSymbolAddress((void**)&p_yg,    g_ygated);

    const int ROWS_INPROJ = QKV + TV + 2 * NVH;  // 12352
    const int DELTA_SMEM = (KD * VD + 3 * KD + 1024 + 16) * sizeof(float);  // ~70KB
    cudaFuncSetAttribute(delta_k, cudaFuncAttributeMaxDynamicSharedMemorySize, DELTA_SMEM);

    // 1. h = rmsnorm(x, in_ln_w)
    rmsnorm_k<<<1, 512>>>(x, in_ln_w, p_h);
    // 2. proj = in_proj_w @ h  (12352 x 2048), fused conv-state update + silu
    inproj_conv_k<<<(ROWS_INPROJ * 32 + 255) / 256, 256>>>(
        in_proj_w, p_h, conv_state, conv_w, out_conv, ROWS_INPROJ);
    // 3. per-head delta rule + gated rmsnorm -> g_ygated, new ssm state
    delta_k<<<NVH, 1024, DELTA_SMEM>>>(ssm_state, A_log, dt_bias, norm_w, out_ssm);
    // 4. x1 = x + out_proj_w @ y_gated   (2048 x 4096)
    matvec_k<TV, true><<<(HID * 32 + 255) / 256, 256>>>(
        out_proj_w, p_yg, x, p_x1, HID);
    // 5. hn = rmsnorm(x1, post_ln_w)
    rmsnorm_k<<<1, 512>>>(p_x1, post_ln_w, p_hn);
    // 6. inter = silu(gate_w@hn) * (up_w@hn)   (2 x 8192 x 2048)
    gateup_k<<<(INTER * 32 + 255) / 256, 256>>>(gate_w, up_w);
    // 7. x_out = x1 + down_w @ inter   (2048 x 8192)
    matvec_k<INTER, true><<<(HID * 32 + 255) / 256, 256>>>(
        down_w, p_inter, p_x1, out_x, HID);
}

// round 6
// speedup vs baseline: 1.3684x; 1.2957x over previous
#include <cuda_runtime.h>
#include <math.h>

#define HID   2048
#define INTER 8192
#define QKV   8192
#define TV    4096
#define NVH   32
#define KD    128
#define VD    128
#define NKH   16
#define CK    4

// ---------------- scratch (device globals; no allocations allowed) ----------
__device__ float g_h[HID];                 // rmsnorm(x)
__device__ float g_proj[QKV + TV + 2*NVH]; // in_proj output (z/a/b part used)
__device__ float g_conv[QKV];              // silu(conv) output
__device__ float g_ygated[TV];             // gated per-head outputs
__device__ float g_x1[HID];                // residual + attn_out
__device__ float g_hn[HID];                // rmsnorm(x1)
__device__ float g_inter[INTER];           // silu(gate)*up

__device__ __forceinline__ float warp_sum(float v) {
#pragma unroll
    for (int o = 16; o; o >>= 1) v += __shfl_down_sync(0xffffffffu, v, o);
    return v;
}

__device__ __forceinline__ float silu(float x) { return x / (1.f + expf(-x)); }

// block-level reduction of one value; result valid on thread 0
template <int TPB>
__device__ __forceinline__ float block_sum(float s, float* red) {
    s = warp_sum(s);
    if ((threadIdx.x & 31) == 0) red[threadIdx.x >> 5] = s;
    __syncthreads();
    float t = 0.f;
    if (threadIdx.x == 0) {
#pragma unroll
        for (int i = 0; i < TPB / 32; i++) t += red[i];
    }
    return t;
}

// ---------------- rmsnorm: out = x * rsqrt(mean(x^2)+eps) * (1+w) ----------
__global__ void rmsnorm_k(const float* __restrict__ x, const float* __restrict__ w,
                          float* __restrict__ out) {
    __shared__ float red[16];
    __shared__ float s_inv;
    int tid = threadIdx.x;
    float ss = 0.f;
    for (int i = tid; i < HID; i += blockDim.x) { float v = x[i]; ss += v * v; }
    ss = warp_sum(ss);
    if ((tid & 31) == 0) red[tid >> 5] = ss;
    __syncthreads();
    if (tid == 0) {
        float t = 0.f;
        for (int i = 0; i < (int)(blockDim.x >> 5); i++) t += red[i];
        s_inv = rsqrtf(t / HID + 1e-6f);
    }
    __syncthreads();
    float inv = s_inv;
    for (int i = tid; i < HID; i += blockDim.x)
        out[i] = x[i] * inv * (1.f + w[i]);
}

// ---------------- block-per-row matvec: y[r] = dot(W[r,:K], v) -------------
template <int K, int TPB, bool RES>
__global__ void rowmv_k(const float* __restrict__ W, const float* __restrict__ v,
                        const float* __restrict__ res, float* __restrict__ y) {
    __shared__ float red[TPB / 32];
    int r = blockIdx.x;
    const float4* Wr = (const float4*)(W + (size_t)r * K);
    const float4* v4 = (const float4*)v;
    float s = 0.f;
#pragma unroll
    for (int i = 0; i < K / 4 / TPB; i++) {
        int idx = threadIdx.x + TPB * i;
        float4 a = Wr[idx];
        float4 b = __ldg(&v4[idx]);
        s += a.x * b.x + a.y * b.y + a.z * b.z + a.w * b.w;
    }
    float tot = block_sum<TPB>(s, red);
    if (threadIdx.x == 0) y[r] = RES ? (res[r] + tot) : tot;
}

// ---------------- in_proj matvec (block/row) w/ fused conv update ----------
__global__ void inproj_conv_k(const float* __restrict__ W, const float* __restrict__ v,
                              const float* __restrict__ cs, const float* __restrict__ cw,
                              float* __restrict__ out_conv_state) {
    __shared__ float red[4];
    int r = blockIdx.x;
    const float4* Wr = (const float4*)(W + (size_t)r * HID);
    const float4* v4 = (const float4*)v;
    float s = 0.f;
#pragma unroll
    for (int i = 0; i < HID / 4 / 128; i++) {  // 4 iters
        int idx = threadIdx.x + 128 * i;
        float4 a = Wr[idx];
        float4 b = __ldg(&v4[idx]);
        s += a.x * b.x + a.y * b.y + a.z * b.z + a.w * b.w;
    }
    float tot = block_sum<128>(s, red);
    if (threadIdx.x == 0) {
        g_proj[r] = tot;
        if (r < QKV) {
            float s1 = cs[r * 4 + 1], s2 = cs[r * 4 + 2], s3 = cs[r * 4 + 3];
            float4 w4 = ((const float4*)cw)[r];
            float acc = s1 * w4.x + s2 * w4.y + s3 * w4.z + tot * w4.w;
            ((float4*)out_conv_state)[r] = make_float4(s1, s2, s3, tot);
            g_conv[r] = silu(acc);
        }
    }
}

// ---------------- gate/up fused, block-per-row -----------------------------
__global__ void gateup_k(const float* __restrict__ G, const float* __restrict__ U) {
    __shared__ float redg[4], redu[4];
    int r = blockIdx.x;
    const float4* g4 = (const float4*)(G + (size_t)r * HID);
    const float4* u4 = (const float4*)(U + (size_t)r * HID);
    const float4* h4 = (const float4*)g_hn;
    float sg = 0.f, su = 0.f;
#pragma unroll
    for (int i = 0; i < HID / 4 / 128; i++) {  // 4 iters
        int idx = threadIdx.x + 128 * i;
        float4 a = g4[idx], b = u4[idx], c = __ldg(&h4[idx]);
        sg += a.x * c.x + a.y * c.y + a.z * c.z + a.w * c.w;
        su += b.x * c.x + b.y * c.y + b.z * c.z + b.w * c.w;
    }
    sg = warp_sum(sg);
    su = warp_sum(su);
    if ((threadIdx.x & 31) == 0) { redg[threadIdx.x >> 5] = sg; redu[threadIdx.x >> 5] = su; }
    __syncthreads();
    if (threadIdx.x == 0) {
        float tg = redg[0] + redg[1] + redg[2] + redg[3];
        float tu = redu[0] + redu[1] + redu[2] + redu[3];
        g_inter[r] = silu(tg) * tu;
    }
}

// ---------------- delta rule per head + gated rmsnorm ----------------------
// block = 1 head, 1024 threads. S (128x128) staged in dynamic SMEM.
__global__ void delta_k(const float* __restrict__ Sin, const float* __restrict__ A_log,
                        const float* __restrict__ dt_bias, const float* __restrict__ norm_w,
                        float* __restrict__ Sout) {
    extern __shared__ float sm[];
    float* Ssh  = sm;                    // 16384
    float* kn   = sm + KD * VD;          // 128
    float* qn   = kn + KD;               // 128
    float* dl   = qn + KD;               // 128
    float* part = dl + KD;               // 1024
    float* red  = part + 1024;           // 4

    int h   = blockIdx.x;
    int tid = threadIdx.x;
    int t   = tid & 127;
    int kg  = tid >> 7;
    int kh  = h >> 1;  // RATIO = 2

    const float4* S4 = (const float4*)(Sin + (size_t)h * KD * VD);
#pragma unroll
    for (int i = 0; i < 4; i++)
        ((float4*)Ssh)[tid + 1024 * i] = S4[tid + 1024 * i];

    float qv = 0.f, kv = 0.f, vv = 0.f;
    if (tid < 128) {
        qv = g_conv[kh * KD + t];
        kv = g_conv[NKH * KD + kh * KD + t];
        vv = g_conv[2 * NKH * KD + h * VD + t];
        float s = warp_sum(qv * qv);
        if ((t & 31) == 0) red[t >> 5] = s;
    }
    __syncthreads();
    if (tid < 128) {
        float qs = red[0] + red[1] + red[2] + red[3];
        qn[t] = qv / fmaxf(sqrtf(qs), 1e-12f);
    }
    __syncthreads();
    if (tid < 128) {
        float s = warp_sum(kv * kv);
        if ((t & 31) == 0) red[t >> 5] = s;
    }
    __syncthreads();
    if (tid < 128) {
        float ks = red[0] + red[1] + red[2] + red[3];
        kn[t] = kv / fmaxf(sqrtf(ks), 1e-12f);
    }
    __syncthreads();

    float a = g_proj[QKV + TV + h];
    float b = g_proj[QKV + TV + NVH + h];
    float beta = 1.f / (1.f + expf(-b));
    float spx = a + dt_bias[h];
    float sp = (spx > 20.f) ? spx : log1pf(expf(spx));
    float decay = expf(-expf(A_log[h]) * sp);

    // pass 1: Sk[t] = sum_k S[k,t]*kn[k], k split over 8 groups
    {
        float s = 0.f;
        int k0 = kg * 16;
#pragma unroll
        for (int k = 0; k < 16; k++) s += Ssh[(k0 + k) * VD + t] * kn[k0 + k];
        part[kg * 128 + t] = s;
    }
    __syncthreads();
    if (tid < 128) {
        float sk = 0.f;
#pragma unroll
        for (int g = 0; g < 8; g++) sk += part[g * 128 + t];
        dl[t] = vv - sk;
    }
    __syncthreads();

    // pass 2: newS (write global) + y partials
    float* So = Sout + (size_t)h * KD * VD;
    {
        float del = dl[t];
        float yp = 0.f;
        int k0 = kg * 16;
#pragma unroll
        for (int k = 0; k < 16; k++) {
            int kk = k0 + k;
            float ns = decay * Ssh[kk * VD + t] + beta * kn[kk] * del;
            So[kk * VD + t] = ns;
            yp += ns * qn[kk];
        }
        part[kg * 128 + t] = yp;
    }
    __syncthreads();

    float y = 0.f;
    if (tid < 128) {
#pragma unroll
        for (int g = 0; g < 8; g++) y += part[g * 128 + t];
        float s = warp_sum(y * y);
        if ((t & 31) == 0) red[t >> 5] = s;
    }
    __syncthreads();
    if (tid < 128) {
        float var = (red[0] + red[1] + red[2] + red[3]) / VD;
        float yn = y * rsqrtf(var + 1e-6f) * norm_w[t];
        float z = g_proj[QKV + h * VD + t];
        g_ygated[h * VD + t] = yn * silu(z);
    }
}

extern "C" void kernel_launch(void* const* d_in, const int* in_sizes, int n_in,
                              void* d_out, int out_size) {
    const float* x          = (const float*)d_in[0];
    const float* conv_state = (const float*)d_in[1];
    const float* ssm_state  = (const float*)d_in[2];
    const float* in_ln_w    = (const float*)d_in[3];
    const float* in_proj_w  = (const float*)d_in[4];
    const float* conv_w     = (const float*)d_in[5];
    const float* A_log      = (const float*)d_in[6];
    const float* dt_bias    = (const float*)d_in[7];
    const float* norm_w     = (const float*)d_in[8];
    const float* out_proj_w = (const float*)d_in[9];
    const float* post_ln_w  = (const float*)d_in[10];
    const float* gate_w     = (const float*)d_in[11];
    const float* up_w       = (const float*)d_in[12];
    const float* down_w     = (const float*)d_in[13];

    float* out        = (float*)d_out;
    float* out_x      = out;                       // 2048
    float* out_conv   = out + HID;                 // 32768
    float* out_ssm    = out + HID + QKV * CK;      // 524288

    float *p_h, *p_x1, *p_hn, *p_inter, *p_yg;
    cudaGetSymbolAddress((void**)&p_h,     g_h);
    cudaGetSymbolAddress((void**)&p_x1,    g_x1);
    cudaGetSymbolAddress((void**)&p_hn,    g_hn);
    cudaGetSymbolAddress((void**)&p_inter, g_inter);
    cudaGetSymbolAddress((void**)&p_yg,    g_ygated);

    const int ROWS_INPROJ = QKV + TV + 2 * NVH;  // 12352
    const int DELTA_SMEM = (KD * VD + 3 * KD + 1024 + 16) * sizeof(float);  // ~70KB
    cudaFuncSetAttribute(delta_k, cudaFuncAttributeMaxDynamicSharedMemorySize, DELTA_SMEM);

    // 1. h = rmsnorm(x, in_ln_w)
    rmsnorm_k<<<1, 512>>>(x, in_ln_w, p_h);
    // 2. proj = in_proj_w @ h  (12352 x 2048), fused conv-state update + silu
    inproj_conv_k<<<ROWS_INPROJ, 128>>>(in_proj_w, p_h, conv_state, conv_w, out_conv);
    // 3. per-head delta rule + gated rmsnorm -> g_ygated, new ssm state
    delta_k<<<NVH, 1024, DELTA_SMEM>>>(ssm_state, A_log, dt_bias, norm_w, out_ssm);
    // 4. x1 = x + out_proj_w @ y_gated   (2048 x 4096)
    rowmv_k<TV, 256, true><<<HID, 256>>>(out_proj_w, p_yg, x, p_x1);
    // 5. hn = rmsnorm(x1, post_ln_w)
    rmsnorm_k<<<1, 512>>>(p_x1, post_ln_w, p_hn);
    // 6. inter = silu(gate_w@hn) * (up_w@hn)   (2 x 8192 x 2048)
    gateup_k<<<INTER, 128>>>(gate_w, up_w);
    // 7. x_out = x1 + down_w @ inter   (2048 x 8192)
    rowmv_k<INTER, 256, true><<<HID, 256>>>(down_w, p_inter, p_x1, out_x);
}

// round 8
// speedup vs baseline: 1.5521x; 1.1343x over previous
#include <cuda_runtime.h>
#include <math.h>

#define HID   2048
#define INTER 8192
#define QKV   8192
#define TV    4096
#define NVH   32
#define KD    128
#define VD    128
#define NKH   16
#define CK    4

// ---------------- scratch (device globals; no allocations allowed) ----------
__device__ float g_h[HID];                 // rmsnorm(x)
__device__ float g_proj[QKV + TV + 2*NVH]; // in_proj output (z/a/b part used)
__device__ float g_conv[QKV];              // silu(conv) output
__device__ float g_ygated[TV];             // gated per-head outputs
__device__ float g_x1[HID];                // residual + attn_out
__device__ float g_hn[HID];                // rmsnorm(x1)
__device__ float g_inter[INTER];           // silu(gate)*up

__device__ __forceinline__ void pdl_wait()    { asm volatile("griddepcontrol.wait;" ::: "memory"); }
__device__ __forceinline__ void pdl_trigger() { asm volatile("griddepcontrol.launch_dependents;" ::: "memory"); }

__device__ __forceinline__ float warp_sum(float v) {
#pragma unroll
    for (int o = 16; o; o >>= 1) v += __shfl_down_sync(0xffffffffu, v, o);
    return v;
}

__device__ __forceinline__ float silu(float x) { return x / (1.f + expf(-x)); }

__device__ __forceinline__ float dot4(float4 a, float4 b) {
    return a.x * b.x + a.y * b.y + a.z * b.z + a.w * b.w;
}

// ---------------- rmsnorm: out = x * rsqrt(mean(x^2)+eps) * (1+w) ----------
__global__ void rmsnorm_k(const float* __restrict__ x, const float* __restrict__ w,
                          float* __restrict__ out) {
    __shared__ float red[16];
    __shared__ float s_inv;
    pdl_wait();
    int tid = threadIdx.x;
    float ss = 0.f;
    for (int i = tid; i < HID; i += blockDim.x) { float v = x[i]; ss += v * v; }
    ss = warp_sum(ss);
    if ((tid & 31) == 0) red[tid >> 5] = ss;
    __syncthreads();
    if (tid == 0) {
        float t = 0.f;
        for (int i = 0; i < (int)(blockDim.x >> 5); i++) t += red[i];
        s_inv = rsqrtf(t / HID + 1e-6f);
    }
    __syncthreads();
    float inv = s_inv;
    for (int i = tid; i < HID; i += blockDim.x)
        out[i] = x[i] * inv * (1.f + w[i]);
    pdl_trigger();
}

// ---------------- block-per-row matvec, IT front-batched loads -------------
// K/4/TPB = IT independent LDG.128 per thread, prefetched before pdl_wait.
template <int K, int TPB, bool RES>
__global__ void __launch_bounds__(TPB) rowmv_k(
        const float* __restrict__ W, const float* __restrict__ v,
        const float* __restrict__ res, float* __restrict__ y) {
    constexpr int IT = K / 4 / TPB;
    __shared__ float red[TPB / 32];
    int r = blockIdx.x;
    const float4* Wr = (const float4*)(W + (size_t)r * K);
    float4 a[IT];
#pragma unroll
    for (int i = 0; i < IT; i++) a[i] = __ldcs(Wr + threadIdx.x + TPB * i);
    pdl_wait();
    const float4* v4 = (const float4*)v;
    float s = 0.f;
#pragma unroll
    for (int i = 0; i < IT; i++) s += dot4(a[i], __ldg(&v4[threadIdx.x + TPB * i]));
    s = warp_sum(s);
    if ((threadIdx.x & 31) == 0) red[threadIdx.x >> 5] = s;
    __syncthreads();
    if (threadIdx.x == 0) {
        float t = 0.f;
#pragma unroll
        for (int i = 0; i < TPB / 32; i++) t += red[i];
        y[r] = RES ? (res[r] + t) : t;
    }
    pdl_trigger();
}

// ---------------- in_proj matvec: 2 rows/block, fused conv update ----------
__global__ void __launch_bounds__(128) inproj_conv_k(
        const float* __restrict__ W, const float* __restrict__ v,
        const float* __restrict__ cs, const float* __restrict__ cw,
        float* __restrict__ out_conv_state) {
    __shared__ float red0[4], red1[4];
    int r0 = blockIdx.x * 2, r1 = r0 + 1;
    const float4* W0 = (const float4*)(W + (size_t)r0 * HID);
    const float4* W1 = (const float4*)(W + (size_t)r1 * HID);
    float4 a0[4], a1[4];
#pragma unroll
    for (int i = 0; i < 4; i++) {
        a0[i] = __ldcs(W0 + threadIdx.x + 128 * i);
        a1[i] = __ldcs(W1 + threadIdx.x + 128 * i);
    }
    pdl_wait();
    const float4* v4 = (const float4*)v;
    float s0 = 0.f, s1 = 0.f;
#pragma unroll
    for (int i = 0; i < 4; i++) {
        float4 b = __ldg(&v4[threadIdx.x + 128 * i]);
        s0 += dot4(a0[i], b);
        s1 += dot4(a1[i], b);
    }
    s0 = warp_sum(s0);
    s1 = warp_sum(s1);
    if ((threadIdx.x & 31) == 0) { red0[threadIdx.x >> 5] = s0; red1[threadIdx.x >> 5] = s1; }
    __syncthreads();
    if (threadIdx.x < 2) {
        int r = threadIdx.x ? r1 : r0;
        float* red = threadIdx.x ? red1 : red0;
        float tot = red[0] + red[1] + red[2] + red[3];
        g_proj[r] = tot;
        if (r < QKV) {
            float c1 = cs[r * 4 + 1], c2 = cs[r * 4 + 2], c3 = cs[r * 4 + 3];
            float4 w4 = ((const float4*)cw)[r];
            float acc = c1 * w4.x + c2 * w4.y + c3 * w4.z + tot * w4.w;
            ((float4*)out_conv_state)[r] = make_float4(c1, c2, c3, tot);
            g_conv[r] = silu(acc);
        }
    }
    pdl_trigger();
}

// ---------------- gate/up fused, block-per-row (8 loads in flight) ---------
__global__ void __launch_bounds__(128) gateup_k(
        const float* __restrict__ G, const float* __restrict__ U) {
    __shared__ float redg[4], redu[4];
    int r = blockIdx.x;
    const float4* g4 = (const float4*)(G + (size_t)r * HID);
    const float4* u4 = (const float4*)(U + (size_t)r * HID);
    float4 ag[4], au[4];
#pragma unroll
    for (int i = 0; i < 4; i++) {
        ag[i] = __ldcs(g4 + threadIdx.x + 128 * i);
        au[i] = __ldcs(u4 + threadIdx.x + 128 * i);
    }
    pdl_wait();
    const float4* h4 = (const float4*)g_hn;
    float sg = 0.f, su = 0.f;
#pragma unroll
    for (int i = 0; i < 4; i++) {
        float4 c = __ldg(&h4[threadIdx.x + 128 * i]);
        sg += dot4(ag[i], c);
        su += dot4(au[i], c);
    }
    sg = warp_sum(sg);
    su = warp_sum(su);
    if ((threadIdx.x & 31) == 0) { redg[threadIdx.x >> 5] = sg; redu[threadIdx.x >> 5] = su; }
    __syncthreads();
    if (threadIdx.x == 0) {
        float tg = redg[0] + redg[1] + redg[2] + redg[3];
        float tu = redu[0] + redu[1] + redu[2] + redu[3];
        g_inter[r] = silu(tg) * tu;
    }
    pdl_trigger();
}

// ---------------- delta rule per head + gated rmsnorm ----------------------
// block = 1 head, 1024 threads. S staged to SMEM before pdl_wait (overlap).
__global__ void delta_k(const float* __restrict__ Sin, const float* __restrict__ A_log,
                        const float* __restrict__ dt_bias, const float* __restrict__ norm_w,
                        float* __restrict__ Sout) {
    extern __shared__ float sm[];
    float* Ssh  = sm;                    // 16384
    float* kn   = sm + KD * VD;          // 128
    float* qn   = kn + KD;               // 128
    float* dl   = qn + KD;               // 128
    float* part = dl + KD;               // 1024
    float* red  = part + 1024;           // 4

    int h   = blockIdx.x;
    int tid = threadIdx.x;
    int t   = tid & 127;
    int kg  = tid >> 7;
    int kh  = h >> 1;  // RATIO = 2

    // stage S (independent of previous kernel) BEFORE the PDL wait
    const float4* S4 = (const float4*)(Sin + (size_t)h * KD * VD);
#pragma unroll
    for (int i = 0; i < 4; i++)
        ((float4*)Ssh)[tid + 1024 * i] = S4[tid + 1024 * i];

    pdl_wait();

    float qv = 0.f, kv = 0.f, vv = 0.f;
    if (tid < 128) {
        qv = g_conv[kh * KD + t];
        kv = g_conv[NKH * KD + kh * KD + t];
        vv = g_conv[2 * NKH * KD + h * VD + t];
        float s = warp_sum(qv * qv);
        if ((t & 31) == 0) red[t >> 5] = s;
    }
    __syncthreads();
    if (tid < 128) {
        float qs = red[0] + red[1] + red[2] + red[3];
        qn[t] = qv / fmaxf(sqrtf(qs), 1e-12f);
    }
    __syncthreads();
    if (tid < 128) {
        float s = warp_sum(kv * kv);
        if ((t & 31) == 0) red[t >> 5] = s;
    }
    __syncthreads();
    if (tid < 128) {
        float ks = red[0] + red[1] + red[2] + red[3];
        kn[t] = kv / fmaxf(sqrtf(ks), 1e-12f);
    }
    __syncthreads();

    float a = g_proj[QKV + TV + h];
    float b = g_proj[QKV + TV + NVH + h];
    float beta = 1.f / (1.f + expf(-b));
    float spx = a + dt_bias[h];
    float sp = (spx > 20.f) ? spx : log1pf(expf(spx));
    float decay = expf(-expf(A_log[h]) * sp);

    // pass 1: Sk[t] = sum_k S[k,t]*kn[k], k split over 8 groups
    {
        float s = 0.f;
        int k0 = kg * 16;
#pragma unroll
        for (int k = 0; k < 16; k++) s += Ssh[(k0 + k) * VD + t] * kn[k0 + k];
        part[kg * 128 + t] = s;
    }
    __syncthreads();
    if (tid < 128) {
        float sk = 0.f;
#pragma unroll
        for (int g = 0; g < 8; g++) sk += part[g * 128 + t];
        dl[t] = vv - sk;
    }
    __syncthreads();

    // pass 2: newS (write global) + y partials
    float* So = Sout + (size_t)h * KD * VD;
    {
        float del = dl[t];
        float yp = 0.f;
        int k0 = kg * 16;
#pragma unroll
        for (int k = 0; k < 16; k++) {
            int kk = k0 + k;
            float ns = decay * Ssh[kk * VD + t] + beta * kn[kk] * del;
            So[kk * VD + t] = ns;
            yp += ns * qn[kk];
        }
        part[kg * 128 + t] = yp;
    }
    __syncthreads();

    float y = 0.f;
    if (tid < 128) {
#pragma unroll
        for (int g = 0; g < 8; g++) y += part[g * 128 + t];
        float s = warp_sum(y * y);
        if ((t & 31) == 0) red[t >> 5] = s;
    }
    __syncthreads();
    if (tid < 128) {
        float var = (red[0] + red[1] + red[2] + red[3]) / VD;
        float yn = y * rsqrtf(var + 1e-6f) * norm_w[t];
        float z = g_proj[QKV + h * VD + t];
        g_ygated[h * VD + t] = yn * silu(z);
    }
    pdl_trigger();
}

// ---------------- host-side PDL launch helper ------------------------------
template <typename F, typename... Args>
static void launch_pdl(F* func, dim3 grid, dim3 block, size_t smem, Args... args) {
    cudaLaunchAttribute attr[1] = {};
    attr[0].id = cudaLaunchAttributeProgrammaticStreamSerialization;
    attr[0].val.programmaticStreamSerializationAllowed = 1;
    cudaLaunchConfig_t cfg = {};
    cfg.gridDim = grid;
    cfg.blockDim = block;
    cfg.dynamicSmemBytes = smem;
    cfg.stream = 0;
    cfg.attrs = attr;
    cfg.numAttrs = 1;
    cudaLaunchKernelEx(&cfg, func, args...);
}

extern "C" void kernel_launch(void* const* d_in, const int* in_sizes, int n_in,
                              void* d_out, int out_size) {
    const float* x          = (const float*)d_in[0];
    const float* conv_state = (const float*)d_in[1];
    const float* ssm_state  = (const float*)d_in[2];
    const float* in_ln_w    = (const float*)d_in[3];
    const float* in_proj_w  = (const float*)d_in[4];
    const float* conv_w     = (const float*)d_in[5];
    const float* A_log      = (const float*)d_in[6];
    const float* dt_bias    = (const float*)d_in[7];
    const float* norm_w     = (const float*)d_in[8];
    const float* out_proj_w = (const float*)d_in[9];
    const float* post_ln_w  = (const float*)d_in[10];
    const float* gate_w     = (const float*)d_in[11];
    const float* up_w       = (const float*)d_in[12];
    const float* down_w     = (const float*)d_in[13];

    float* out        = (float*)d_out;
    float* out_x      = out;                       // 2048
    float* out_conv   = out + HID;                 // 32768
    float* out_ssm    = out + HID + QKV * CK;      // 524288

    float *p_h, *p_x1, *p_hn, *p_inter, *p_yg;
    cudaGetSymbolAddress((void**)&p_h,     g_h);
    cudaGetSymbolAddress((void**)&p_x1,    g_x1);
    cudaGetSymbolAddress((void**)&p_hn,    g_hn);
    cudaGetSymbolAddress((void**)&p_inter, g_inter);
    cudaGetSymbolAddress((void**)&p_yg,    g_ygated);

    const int ROWS_INPROJ = QKV + TV + 2 * NVH;  // 12352
    const int DELTA_SMEM = (KD * VD + 3 * KD + 1024 + 16) * sizeof(float);  // ~70KB
    cudaFuncSetAttribute(delta_k, cudaFuncAttributeMaxDynamicSharedMemorySize, DELTA_SMEM);

    // 1. h = rmsnorm(x, in_ln_w)
    launch_pdl(rmsnorm_k, 1, 512, 0, x, in_ln_w, p_h);
    // 2. proj = in_proj_w @ h  (12352 x 2048), fused conv update, 2 rows/block
    launch_pdl(inproj_conv_k, ROWS_INPROJ / 2, 128, 0,
               in_proj_w, (const float*)p_h, conv_state, conv_w, out_conv);
    // 3. per-head delta rule + gated rmsnorm -> g_ygated, new ssm state
    launch_pdl(delta_k, NVH, 1024, (size_t)DELTA_SMEM,
               ssm_state, A_log, dt_bias, norm_w, out_ssm);
    // 4. x1 = x + out_proj_w @ y_gated   (2048 x 4096), 8 loads/thread
    launch_pdl(rowmv_k<TV, 128, true>, HID, 128, 0,
               out_proj_w, (const float*)p_yg, x, p_x1);
    // 5. hn = rmsnorm(x1, post_ln_w)
    launch_pdl(rmsnorm_k, 1, 512, 0, (const float*)p_x1, post_ln_w, p_hn);
    // 6. inter = silu(gate_w@hn) * (up_w@hn)   (2 x 8192 x 2048)
    launch_pdl(gateup_k, INTER, 128, 0, gate_w, up_w);
    // 7. x_out = x1 + down_w @ inter   (2048 x 8192), 8 loads/thread
    launch_pdl(rowmv_k<INTER, 256, true>, HID, 256, 0,
               down_w, (const float*)p_inter, (const float*)p_x1, out_x);
}